// round 5
// baseline (speedup 1.0000x reference)
#include <cuda_runtime.h>
#include <math.h>

typedef unsigned long long ull;

#define NT 10
#define NL 16
#define NNODES 31
#define BB 4096
#define G4 1024
#define NTHR 512

// smem layout in floats
#define PW 260                        // W row pitch (16B aligned, conflict-free)
#define PRR 132                       // sR row pitch per (ks, combo)
#define OFF_W 0                       // 128 rows x PW
#define OFF_H (128 * PW)              // 10 combos x 256
#define OFF_R (OFF_H + 10 * 256)      // 4 kslices x 10 combos x PRR
#define SMEM_FLOATS (OFF_R + 4 * 10 * PRR)
#define SMEM_BYTES (SMEM_FLOATS * 4)

__device__ __align__(16) float g_XG[310 * G4];
__device__ __align__(16) float g_H[2][160 * 256];
__device__ int g_leaf[BB * NT];

__device__ __forceinline__ float sigf(float x) { return 1.0f / (1.0f + __expf(-x)); }

__device__ __forceinline__ void fma2(ull& d, ull a, ull b) {
    asm("fma.rn.f32x2 %0, %1, %2, %0;" : "+l"(d) : "l"(a), "l"(b));
}
__device__ __forceinline__ float sum2(ull v) {
    float2 f = *(float2*)&v;
    return f.x + f.y;
}
__device__ __forceinline__ void cluster_sync() {
    asm volatile("barrier.cluster.arrive.aligned;" ::: "memory");
    asm volatile("barrier.cluster.wait.aligned;" ::: "memory");
}

// ---------------------------------------------------------------------------
// XG[n][j] = emb[n] . W_ih[j] + b_ih[j] + b_hh[j]   (M=310, N=1024, K=256)
// ---------------------------------------------------------------------------
__global__ void xg_kernel(const float* __restrict__ emb,
                          const float* __restrict__ W_ih,
                          const float* __restrict__ b_ih,
                          const float* __restrict__ b_hh) {
    __shared__ float sE[32][65];
    __shared__ float sW[64][65];
    const int n0 = blockIdx.x * 64;
    const int m0 = blockIdx.y * 32;
    const int tid = threadIdx.x;
    const int tm = tid >> 4, tn = tid & 15;
    float acc[2][4] = {};

    for (int k0 = 0; k0 < 256; k0 += 64) {
        for (int i = tid; i < 512; i += 256) {
            int r = i >> 4, c4 = i & 15;
            int gm = m0 + r;
            float4 v = (gm < 310)
                     ? *(const float4*)(emb + gm * 256 + k0 + c4 * 4)
                     : make_float4(0.f, 0.f, 0.f, 0.f);
            sE[r][c4*4+0] = v.x; sE[r][c4*4+1] = v.y;
            sE[r][c4*4+2] = v.z; sE[r][c4*4+3] = v.w;
        }
        for (int i = tid; i < 1024; i += 256) {
            int r = i >> 4, c4 = i & 15;
            float4 v = *(const float4*)(W_ih + (n0 + r) * 256 + k0 + c4 * 4);
            sW[r][c4*4+0] = v.x; sW[r][c4*4+1] = v.y;
            sW[r][c4*4+2] = v.z; sW[r][c4*4+3] = v.w;
        }
        __syncthreads();
        #pragma unroll
        for (int k = 0; k < 64; ++k) {
            float e0 = sE[tm*2+0][k], e1 = sE[tm*2+1][k];
            float w0 = sW[tn*4+0][k], w1 = sW[tn*4+1][k];
            float w2 = sW[tn*4+2][k], w3 = sW[tn*4+3][k];
            acc[0][0] += e0*w0; acc[0][1] += e0*w1; acc[0][2] += e0*w2; acc[0][3] += e0*w3;
            acc[1][0] += e1*w0; acc[1][1] += e1*w1; acc[1][2] += e1*w2; acc[1][3] += e1*w3;
        }
        __syncthreads();
    }
    #pragma unroll
    for (int mm = 0; mm < 2; ++mm) {
        int m = m0 + tm*2 + mm;
        if (m >= 310) continue;
        #pragma unroll
        for (int nn = 0; nn < 4; ++nn) {
            int n = n0 + tn*4 + nn;
            g_XG[m * G4 + n] = acc[mm][nn] + b_ih[n] + b_hh[n];
        }
    }
}

// ---------------------------------------------------------------------------
// Persistent LSTM. Grid (8,16), cluster (8,1,1): cluster = the 8 d-split
// blocks of one combo-group cy (10 combos). All sync is intra-cluster HW
// barrier. Block (dx,cy): 128 gate-rows for d-slice d0=dx*32.
// Warp (rg,ks): rows rg*32+lane, all 10 combos, K-slice ks*64. W in smem
// once (128KB), C in registers, h via L2 (stcg/ldcg across cluster barrier).
// ---------------------------------------------------------------------------
__global__ void __launch_bounds__(NTHR, 1) __cluster_dims__(8, 1, 1)
lstm_kernel(const float* __restrict__ W_hh) {
    extern __shared__ __align__(16) float sm[];
    float* sW = sm + OFF_W;
    float* sh = sm + OFF_H;
    float* sR = sm + OFF_R;

    const int tid = threadIdx.x;
    const int dx = blockIdx.x;      // 0..7  (d-slice)
    const int cy = blockIdx.y;      // 0..15 (combo group)
    const int d0 = dx << 5;

    // Cache W_hh slice: 128 rows, row r: j = (r>>5)*256 + d0 + (r&31).
    for (int i = tid; i < 8192; i += NTHR) {
        int row = i >> 6, q = i & 63;
        int j = ((row >> 5) << 8) + d0 + (row & 31);
        *(float4*)(sW + row * PW + q * 4) = ((const float4*)W_hh)[j * 64 + q];
    }

    // Finalize ownership (tid < 320): combo lc = tid>>5, d-lane dl = tid&31.
    const int lc = tid >> 5, dl = tid & 31;
    const int c = cy * 10 + lc;
    const int d = d0 + dl;
    const int tree = c >> 4, leaf = c & 15;

    // ---- Step 0 (h0 = c0 = 0) ----
    float cst = 0.f;
    if (tid < 320) {
        const float* xg = g_XG + (tree * NNODES) * G4;
        float gi = __ldg(xg + d), gg = __ldg(xg + 512 + d), go = __ldg(xg + 768 + d);
        cst = sigf(gi) * tanhf(gg);
        float h = sigf(go) * tanhf(cst);
        __stcg(&g_H[0][c * 256 + d], h);
    }
    cluster_sync();

    // Warp tiling for the recurrent GEMM.
    const int w = tid >> 5, lane = tid & 31;
    const int rg = w & 3;            // row group: rows rg*32+lane
    const int ks = w >> 2;           // K slice: k = ks*64..+63
    const int r = rg * 32 + lane;
    const float* Wr = sW + r * PW + ks * 64;
    const float* hb = sh + ks * 64;
    float* rb = sR + ks * (10 * PRR);

    #pragma unroll
    for (int t = 1; t <= 4; ++t) {
        const int bin = 1 - (t & 1), bout = t & 1;

        // Load h tile (10 x 256) from L2.
        {
            const float4* src = (const float4*)(g_H[bin] + cy * 2560);
            float4* dst = (float4*)sh;
            for (int i = tid; i < 640; i += NTHR) dst[i] = __ldcg(src + i);
        }
        __syncthreads();

        ull acc[10] = {};
        #pragma unroll
        for (int kq = 0; kq < 16; ++kq) {
            ulonglong2 wv = *(const ulonglong2*)(Wr + kq * 4);
            #pragma unroll
            for (int i = 0; i < 10; ++i) {
                ulonglong2 hv = *(const ulonglong2*)(hb + i * 256 + kq * 4);
                fma2(acc[i], wv.x, hv.x);
                fma2(acc[i], wv.y, hv.y);
            }
        }
        #pragma unroll
        for (int i = 0; i < 10; ++i) rb[i * PRR + r] = sum2(acc[i]);
        __syncthreads();

        if (tid < 320) {
            int local = ((1 << t) - 1) + (leaf >> (4 - t));
            const float* xg = g_XG + (tree * NNODES + local) * G4;
            const float* rr = sR + lc * PRR + dl;
            float gi = rr[0]  + rr[1320]      + rr[2640]      + rr[3960];
            float gf = rr[32] + rr[1320 + 32] + rr[2640 + 32] + rr[3960 + 32];
            float gg = rr[64] + rr[1320 + 64] + rr[2640 + 64] + rr[3960 + 64];
            float go = rr[96] + rr[1320 + 96] + rr[2640 + 96] + rr[3960 + 96];
            gi += __ldg(xg + d);       gf += __ldg(xg + 256 + d);
            gg += __ldg(xg + 512 + d); go += __ldg(xg + 768 + d);
            cst = sigf(gf) * cst + sigf(gi) * tanhf(gg);
            float h = sigf(go) * tanhf(cst);
            __stcg(&g_H[bout][c * 256 + d], h);
        }
        if (t < 4) cluster_sync();
    }
}

// ---------------------------------------------------------------------------
// Leaf index per (b, tree) row: ballot over 16-lane groups.
// ---------------------------------------------------------------------------
__global__ void leaf_kernel(const float* __restrict__ cross) {
    int gid = blockIdx.x * 256 + threadIdx.x;
    float v = cross[gid];
    unsigned m = __ballot_sync(0xffffffffu, v > 0.5f);
    int lane = threadIdx.x & 31;
    unsigned m16 = (m >> (lane & 16)) & 0xFFFFu;
    if ((lane & 15) == 0) g_leaf[gid >> 4] = __ffs(m16) - 1;
}

// ---------------------------------------------------------------------------
// Gather: one thread per output float4.
// ---------------------------------------------------------------------------
__global__ void gather_kernel(float4* __restrict__ out) {
    int gid = blockIdx.x * 256 + threadIdx.x;
    int row = gid >> 6, q = gid & 63;
    int lf = g_leaf[row];
    int tr = row - (row / NT) * NT;
    const float4* H4 = (const float4*)g_H[0];
    out[gid] = __ldg(H4 + ((tr << 4) + lf) * 64 + q);
}

// ---------------------------------------------------------------------------
extern "C" void kernel_launch(void* const* d_in, const int* in_sizes, int n_in,
                              void* d_out, int out_size) {
    const float* cross = (const float*)d_in[0];
    const float* emb   = (const float*)d_in[1];
    const float* W_ih  = (const float*)d_in[2];
    const float* W_hh  = (const float*)d_in[3];
    const float* b_ih  = (const float*)d_in[4];
    const float* b_hh  = (const float*)d_in[5];

    static int attr_done = 0;
    if (!attr_done) {
        cudaFuncSetAttribute(lstm_kernel,
                             cudaFuncAttributeMaxDynamicSharedMemorySize,
                             SMEM_BYTES);
        attr_done = 1;
    }

    xg_kernel<<<dim3(16, 10), 256>>>(emb, W_ih, b_ih, b_hh);
    leaf_kernel<<<BB * NT * NL / 256, 256>>>(cross);
    lstm_kernel<<<dim3(8, 16), NTHR, SMEM_BYTES>>>(W_hh);
    gather_kernel<<<BB * NT * 64 / 256, 256>>>((float4*)d_out);
}

// round 6
// speedup vs baseline: 1.1774x; 1.1774x over previous
#include <cuda_runtime.h>
#include <math.h>

typedef unsigned long long ull;

#define NT 10
#define NL 16
#define NNODES 31
#define BB 4096
#define G4 1024
#define NTHR 512

// smem layout in floats (sR aliases sh: never live simultaneously)
#define PW 260                       // W row pitch (16B aligned, conflict-free)
#define OFF_W 0                      // 64 rows x PW
#define OFF_H (64 * PW)              // 20 combos x 256  == 4 ks x 20 combos x 64
#define SMEM_FLOATS (OFF_H + 20 * 256)
#define SMEM_BYTES (SMEM_FLOATS * 4)   // 87,040 B

__device__ __align__(16) float g_XG[310 * G4];
__device__ __align__(16) float g_H[2][160 * 256];
__device__ unsigned g_cnt[8 * 32];   // per-cy barrier, 128B-padded
__device__ unsigned g_gen[8 * 32];

__device__ __forceinline__ float sigf(float x) { return 1.0f / (1.0f + __expf(-x)); }

__device__ __forceinline__ void fma2(ull& d, ull a, ull b) {
    asm("fma.rn.f32x2 %0, %1, %2, %0;" : "+l"(d) : "l"(a), "l"(b));
}
__device__ __forceinline__ float sum2(ull v) {
    float2 f = *(float2*)&v;
    return f.x + f.y;
}

// Barrier across the 16 dx-blocks sharing one cy (all resident).
__device__ __forceinline__ void cybar(int cy, unsigned& target) {
    __syncthreads();
    if (threadIdx.x == 0) {
        target += 1;
        __threadfence();
        if (atomicAdd(&g_cnt[cy * 32], 1) == 15) {
            g_cnt[cy * 32] = 0;
            __threadfence();
            atomicAdd(&g_gen[cy * 32], 1);
        } else {
            while ((int)(*(volatile unsigned*)&g_gen[cy * 32] - target) < 0)
                __nanosleep(32);
            __threadfence();
        }
    }
    __syncthreads();
}

// ---------------------------------------------------------------------------
// XG[n][j] = emb[n] . W_ih[j] + b_ih[j] + b_hh[j]   (M=310, N=1024, K=256)
// ---------------------------------------------------------------------------
__global__ void xg_kernel(const float* __restrict__ emb,
                          const float* __restrict__ W_ih,
                          const float* __restrict__ b_ih,
                          const float* __restrict__ b_hh) {
    __shared__ float sE[32][65];
    __shared__ float sW[64][65];
    const int n0 = blockIdx.x * 64;
    const int m0 = blockIdx.y * 32;
    const int tid = threadIdx.x;
    const int tm = tid >> 4, tn = tid & 15;
    float acc[2][4] = {};

    for (int k0 = 0; k0 < 256; k0 += 64) {
        for (int i = tid; i < 512; i += 256) {
            int r = i >> 4, c4 = i & 15;
            int gm = m0 + r;
            float4 v = (gm < 310)
                     ? *(const float4*)(emb + gm * 256 + k0 + c4 * 4)
                     : make_float4(0.f, 0.f, 0.f, 0.f);
            sE[r][c4*4+0] = v.x; sE[r][c4*4+1] = v.y;
            sE[r][c4*4+2] = v.z; sE[r][c4*4+3] = v.w;
        }
        for (int i = tid; i < 1024; i += 256) {
            int r = i >> 4, c4 = i & 15;
            float4 v = *(const float4*)(W_ih + (n0 + r) * 256 + k0 + c4 * 4);
            sW[r][c4*4+0] = v.x; sW[r][c4*4+1] = v.y;
            sW[r][c4*4+2] = v.z; sW[r][c4*4+3] = v.w;
        }
        __syncthreads();
        #pragma unroll
        for (int k = 0; k < 64; ++k) {
            float e0 = sE[tm*2+0][k], e1 = sE[tm*2+1][k];
            float w0 = sW[tn*4+0][k], w1 = sW[tn*4+1][k];
            float w2 = sW[tn*4+2][k], w3 = sW[tn*4+3][k];
            acc[0][0] += e0*w0; acc[0][1] += e0*w1; acc[0][2] += e0*w2; acc[0][3] += e0*w3;
            acc[1][0] += e1*w0; acc[1][1] += e1*w1; acc[1][2] += e1*w2; acc[1][3] += e1*w3;
        }
        __syncthreads();
    }
    #pragma unroll
    for (int mm = 0; mm < 2; ++mm) {
        int m = m0 + tm*2 + mm;
        if (m >= 310) continue;
        #pragma unroll
        for (int nn = 0; nn < 4; ++nn) {
            int n = n0 + tn*4 + nn;
            g_XG[m * G4 + n] = acc[mm][nn] + b_ih[n] + b_hh[n];
        }
    }
}

// ---------------------------------------------------------------------------
// Persistent LSTM. Grid (16,8)=128 blocks, 512 thr (16 warps), 1 block/SM.
// Block (dx,cy): 64 gate-rows for d-slice d0=dx*16, combos cy*20..+19.
// Warp tile: 32 rows (rg) x 10 combos (cs) x 64-K slice (ks). Partials go to
// sR (aliased onto sh after a sync), summed in the finalize. C in registers;
// h ping-pongs via L2 (stcg/ldcg).
// ---------------------------------------------------------------------------
__global__ void __launch_bounds__(NTHR, 1)
lstm_kernel(const float* __restrict__ W_hh) {
    extern __shared__ __align__(16) float sm[];
    float* sW = sm + OFF_W;
    float* sh = sm + OFF_H;
    float* sR = sm + OFF_H;      // alias: sR live only after sh reads finish

    const int tid = threadIdx.x;
    const int dx = blockIdx.x;      // 0..15
    const int cy = blockIdx.y;      // 0..7
    const int d0 = dx << 4;

    unsigned target = 0;
    if (tid == 0) target = *((volatile unsigned*)&g_gen[cy * 32]);

    // Cache W_hh slice: row r (0..63): j = (r>>4)*256 + d0 + (r&15).
    for (int i = tid; i < 4096; i += NTHR) {
        int row = i >> 6, q = i & 63;
        int j = ((row >> 4) << 8) + d0 + (row & 15);
        *(float4*)(sW + row * PW + q * 4) = ((const float4*)W_hh)[j * 64 + q];
    }

    // Finalize-thread ownership (tid < 320): combo lc, d-lane dl.
    const int lc = tid >> 4, dl = tid & 15;
    const int c = cy * 20 + lc;
    const int d = d0 + dl;
    const int tree = c >> 4, leaf = c & 15;

    // ---- Step 0 (h0 = c0 = 0) ----
    float cst = 0.f;
    if (tid < 320) {
        const float* xg = g_XG + (tree * NNODES) * G4;
        float gi = xg[d], gg = xg[512 + d], go = xg[768 + d];
        cst = sigf(gi) * tanhf(gg);
        float h = sigf(go) * tanhf(cst);
        __stcg(&g_H[0][c * 256 + d], h);
    }
    cybar(cy, target);

    // Warp tiling for the recurrent GEMM.
    const int w = tid >> 5, lane = tid & 31;
    const int rg = w & 1;            // row group: rows rg*32+lane
    const int cs = (w >> 1) & 1;     // combo half: combos cs*10..+9
    const int ks = w >> 2;           // K slice: k = ks*64..+63
    const int r = rg * 32 + lane;    // gate-row = gate*16 + dl
    const float* Wr = sW + r * PW + ks * 64;
    const float* hb = sh + cs * 10 * 256 + ks * 64;
    float* rb = sR + ks * 1280 + cs * 640;   // [ks][combo][row]

    #pragma unroll
    for (int t = 1; t <= 4; ++t) {
        const int bin = 1 - (t & 1), bout = t & 1;

        // Load h tile (20 x 256) from L2.
        {
            const float4* src = (const float4*)(g_H[bin] + cy * 5120);
            float4* dst = (float4*)sh;
            for (int i = tid; i < 1280; i += NTHR) dst[i] = __ldcg(src + i);
        }
        __syncthreads();

        ull acc[10] = {};
        #pragma unroll
        for (int kq = 0; kq < 16; ++kq) {
            ulonglong2 wv = *(const ulonglong2*)(Wr + kq * 4);
            #pragma unroll
            for (int i = 0; i < 10; ++i) {
                ulonglong2 hv = *(const ulonglong2*)(hb + i * 256 + kq * 4);
                fma2(acc[i], wv.x, hv.x);
                fma2(acc[i], wv.y, hv.y);
            }
        }
        __syncthreads();              // all warps done reading sh -> reuse as sR
        #pragma unroll
        for (int i = 0; i < 10; ++i) rb[i * 64 + r] = sum2(acc[i]);
        __syncthreads();

        if (tid < 320) {
            int local = ((1 << t) - 1) + (leaf >> (4 - t));
            const float* xg = g_XG + (tree * NNODES + local) * G4;
            const float* rr = sR + lc * 64 + dl;
            float gi = 0.f, gf = 0.f, gg = 0.f, go = 0.f;
            #pragma unroll
            for (int kk = 0; kk < 4; ++kk) {
                gi += rr[kk * 1280 +  0];
                gf += rr[kk * 1280 + 16];
                gg += rr[kk * 1280 + 32];
                go += rr[kk * 1280 + 48];
            }
            gi += xg[d]; gf += xg[256 + d]; gg += xg[512 + d]; go += xg[768 + d];
            cst = sigf(gf) * cst + sigf(gi) * tanhf(gg);
            float h = sigf(go) * tanhf(cst);
            __stcg(&g_H[bout][c * 256 + d], h);
        }
        if (t < 4) cybar(cy, target);
    }
}

// ---------------------------------------------------------------------------
// Fused leaf+gather: 16 threads per (b,tree) row. Each thread reads one
// one-hot float, finds the leaf via shfl-max, then copies 4 float4s.
// ---------------------------------------------------------------------------
__global__ void gather_kernel(const float* __restrict__ cross,
                              float4* __restrict__ out) {
    int t = blockIdx.x * 256 + threadIdx.x;     // 0..655359
    int row = t >> 4;                           // (b, tree) 0..40959
    int s = t & 15;                             // sub-slot within row
    float v = cross[t];                         // one-hot element s of row
    int val = (v > 0.5f) ? s : -1;
    val = max(val, __shfl_xor_sync(0xffffffffu, val, 1));
    val = max(val, __shfl_xor_sync(0xffffffffu, val, 2));
    val = max(val, __shfl_xor_sync(0xffffffffu, val, 4));
    val = max(val, __shfl_xor_sync(0xffffffffu, val, 8));  // = leaf for row
    int tr = row - (row / NT) * NT;
    const float4* src = (const float4*)g_H[0] + ((tr << 4) + val) * 64 + s * 4;
    float4* dst = out + (size_t)row * 64 + s * 4;
    float4 a = __ldg(src + 0);
    float4 b = __ldg(src + 1);
    float4 c2 = __ldg(src + 2);
    float4 d2 = __ldg(src + 3);
    dst[0] = a; dst[1] = b; dst[2] = c2; dst[3] = d2;
}

// ---------------------------------------------------------------------------
extern "C" void kernel_launch(void* const* d_in, const int* in_sizes, int n_in,
                              void* d_out, int out_size) {
    const float* cross = (const float*)d_in[0];
    const float* emb   = (const float*)d_in[1];
    const float* W_ih  = (const float*)d_in[2];
    const float* W_hh  = (const float*)d_in[3];
    const float* b_ih  = (const float*)d_in[4];
    const float* b_hh  = (const float*)d_in[5];

    static int attr_done = 0;
    if (!attr_done) {
        cudaFuncSetAttribute(lstm_kernel,
                             cudaFuncAttributeMaxDynamicSharedMemorySize,
                             SMEM_BYTES);
        attr_done = 1;
    }

    xg_kernel<<<dim3(16, 10), 256>>>(emb, W_ih, b_ih, b_hh);
    lstm_kernel<<<dim3(16, 8), NTHR, SMEM_BYTES>>>(W_hh);
    gather_kernel<<<BB * NT * NL / 256, 256>>>(cross, (float4*)d_out);
}

// round 7
// speedup vs baseline: 1.3247x; 1.1251x over previous
#include <cuda_runtime.h>
#include <math.h>

typedef unsigned long long ull;

#define NT 10
#define NL 16
#define NNODES 31
#define BB 4096
#define G4 1024
#define NTHR 512

// lstm smem layout in floats (R4-proven)
#define PW 260                       // W row pitch (16B aligned, conflict-free)
#define PR 80                        // sR combo pitch
#define OFF_W 0                      // 64 rows x PW
#define OFF_H (64 * PW)              // 20 combos x 256
#define OFF_R (OFF_H + 20 * 256)     // 4 kslices x 20 combos x PR
#define SMEM_FLOATS (OFF_R + 4 * 20 * PR)
#define SMEM_BYTES (SMEM_FLOATS * 4)

__device__ __align__(16) float g_XGA[310 * G4];   // k-half 0 (+bias)
__device__ __align__(16) float g_XGB[310 * G4];   // k-half 1
__device__ __align__(16) float g_H[2][160 * 256];
__device__ int g_leaf[BB * NT];
__device__ unsigned g_cnt[8 * 32];
__device__ unsigned g_gen[8 * 32];

__device__ __forceinline__ float sigf(float x) { return 1.0f / (1.0f + __expf(-x)); }

__device__ __forceinline__ void fma2(ull& d, ull a, ull b) {
    asm("fma.rn.f32x2 %0, %1, %2, %0;" : "+l"(d) : "l"(a), "l"(b));
}
__device__ __forceinline__ float sum2(ull v) {
    float2 f = *(float2*)&v;
    return f.x + f.y;
}

// Barrier across the 16 dx-blocks sharing one cy (all resident).
__device__ __forceinline__ void cybar(int cy, unsigned& target) {
    __syncthreads();
    if (threadIdx.x == 0) {
        target += 1;
        __threadfence();
        if (atomicAdd(&g_cnt[cy * 32], 1) == 15) {
            g_cnt[cy * 32] = 0;
            __threadfence();
            atomicAdd(&g_gen[cy * 32], 1);
        } else {
            while ((int)(*(volatile unsigned*)&g_gen[cy * 32] - target) < 0)
                __nanosleep(32);
            __threadfence();
        }
    }
    __syncthreads();
}

// ---------------------------------------------------------------------------
// xg: XG[m][j] = emb[m] . W_ih[j] (+ bias on kz=0), K-split in 2 halves.
// Grid (8 colblk x 10 nodeblk x 2 ksplit), 256 thr. Block: 32 nodes x 128
// cols x K=128 (2 chunks of 64). Thread (ty,tx): 4 nodes (ty*4+i) x 4 cols
// (tx+32j). e reads are warp-uniform broadcasts; w reads are stride-1
// conflict-free from a k-major transposed tile.
// ---------------------------------------------------------------------------
#define PE 66          // sE pitch
#define PWX 132        // sW pitch (k-major rows)
__global__ void __launch_bounds__(256)
xg_kernel(const float* __restrict__ emb,
          const float* __restrict__ W_ih,
          const float* __restrict__ b_ih,
          const float* __restrict__ b_hh) {
    __shared__ float sE[32 * PE];        // 32 nodes x 64 k
    __shared__ float sW[64 * PWX];       // 64 k x 128 cols
    const int tid = threadIdx.x;
    const int cb = blockIdx.x;           // col block: cols cb*128..+127
    const int mb = blockIdx.y;           // node block: nodes mb*32..+31
    const int kz = blockIdx.z;           // k half: k = kz*128..+127
    const int ty = tid >> 5, tx = tid & 31;

    float acc[4][4] = {};

    #pragma unroll
    for (int kc = 0; kc < 2; ++kc) {
        const int k0 = kz * 128 + kc * 64;
        // sE: 32 nodes x 64 k  (512 float4)
        for (int idx = tid; idx < 512; idx += 256) {
            int r = idx >> 4, q = idx & 15;
            int m = mb * 32 + r;
            float4 v = (m < 310)
                     ? *(const float4*)(emb + m * 256 + k0 + q * 4)
                     : make_float4(0.f, 0.f, 0.f, 0.f);
            sE[r * PE + q*4+0] = v.x; sE[r * PE + q*4+1] = v.y;
            sE[r * PE + q*4+2] = v.z; sE[r * PE + q*4+3] = v.w;
        }
        // sW transposed: read W_ih[col][k] float4 along k, scatter to sW[k][col]
        for (int idx = tid; idx < 2048; idx += 256) {
            int cl = idx >> 4, q = idx & 15;
            float4 v = *(const float4*)(W_ih + (cb * 128 + cl) * 256 + k0 + q * 4);
            sW[(q*4+0) * PWX + cl] = v.x;
            sW[(q*4+1) * PWX + cl] = v.y;
            sW[(q*4+2) * PWX + cl] = v.z;
            sW[(q*4+3) * PWX + cl] = v.w;
        }
        __syncthreads();
        #pragma unroll
        for (int k = 0; k < 64; ++k) {
            float e0 = sE[(ty*4+0) * PE + k];
            float e1 = sE[(ty*4+1) * PE + k];
            float e2 = sE[(ty*4+2) * PE + k];
            float e3 = sE[(ty*4+3) * PE + k];
            float w0 = sW[k * PWX + tx];
            float w1 = sW[k * PWX + tx + 32];
            float w2 = sW[k * PWX + tx + 64];
            float w3 = sW[k * PWX + tx + 96];
            acc[0][0] += e0*w0; acc[0][1] += e0*w1; acc[0][2] += e0*w2; acc[0][3] += e0*w3;
            acc[1][0] += e1*w0; acc[1][1] += e1*w1; acc[1][2] += e1*w2; acc[1][3] += e1*w3;
            acc[2][0] += e2*w0; acc[2][1] += e2*w1; acc[2][2] += e2*w2; acc[2][3] += e2*w3;
            acc[3][0] += e3*w0; acc[3][1] += e3*w1; acc[3][2] += e3*w2; acc[3][3] += e3*w3;
        }
        __syncthreads();
    }

    float* dst = kz ? g_XGB : g_XGA;
    #pragma unroll
    for (int i = 0; i < 4; ++i) {
        int m = mb * 32 + ty * 4 + i;
        if (m >= 310) break;
        #pragma unroll
        for (int j = 0; j < 4; ++j) {
            int col = cb * 128 + tx + 32 * j;
            float v = acc[i][j];
            if (kz == 0) v += b_ih[col] + b_hh[col];
            dst[m * G4 + col] = v;
        }
    }
}

// ---------------------------------------------------------------------------
// Persistent LSTM (R4-proven shape). Grid (16,8), 512 thr, 1 block/SM.
// ---------------------------------------------------------------------------
__global__ void __launch_bounds__(NTHR, 1)
lstm_kernel(const float* __restrict__ W_hh) {
    extern __shared__ __align__(16) float sm[];
    float* sW = sm + OFF_W;
    float* sh = sm + OFF_H;
    float* sR = sm + OFF_R;

    const int tid = threadIdx.x;
    const int dx = blockIdx.x;      // 0..15
    const int cy = blockIdx.y;      // 0..7
    const int d0 = dx << 4;

    unsigned target = 0;
    if (tid == 0) target = *((volatile unsigned*)&g_gen[cy * 32]);

    // Cache W_hh slice: row r: j = (r>>4)*256 + d0 + (r&15), k = 0..255.
    for (int i = tid; i < 4096; i += NTHR) {
        int row = i >> 6, q = i & 63;
        int j = ((row >> 4) << 8) + d0 + (row & 15);
        *(float4*)(sW + row * PW + q * 4) = ((const float4*)W_hh)[j * 64 + q];
    }

    const int lc = tid >> 4, dl = tid & 15;
    const int c = cy * 20 + lc;
    const int d = d0 + dl;
    const int tree = c >> 4, leaf = c & 15;

    // ---- Step 0 (h0 = c0 = 0) ----
    float cst = 0.f;
    if (tid < 320) {
        const float* xa = g_XGA + (tree * NNODES) * G4;
        const float* xb = g_XGB + (tree * NNODES) * G4;
        float gi = xa[d] + xb[d];
        float gg = xa[512 + d] + xb[512 + d];
        float go = xa[768 + d] + xb[768 + d];
        cst = sigf(gi) * tanhf(gg);
        float h = sigf(go) * tanhf(cst);
        __stcg(&g_H[0][c * 256 + d], h);
    }
    cybar(cy, target);

    const int w = tid >> 5, lane = tid & 31;
    const int rg = w & 1;
    const int cs = (w >> 1) & 1;
    const int ks = w >> 2;
    const int r = rg * 32 + lane;
    const float* Wr = sW + r * PW + ks * 64;
    const float* hb = sh + cs * 10 * 256 + ks * 64;
    float* rb = sR + ks * (20 * PR) + cs * 10 * PR;

    #pragma unroll
    for (int t = 1; t <= 4; ++t) {
        const int bin = 1 - (t & 1), bout = t & 1;

        {
            const float4* src = (const float4*)(g_H[bin] + cy * 5120);
            float4* dst = (float4*)sh;
            for (int i = tid; i < 1280; i += NTHR) dst[i] = __ldcg(src + i);
        }
        __syncthreads();

        ull acc[10] = {};
        #pragma unroll
        for (int kq = 0; kq < 16; ++kq) {
            ulonglong2 wv = *(const ulonglong2*)(Wr + kq * 4);
            #pragma unroll
            for (int i = 0; i < 10; ++i) {
                ulonglong2 hv = *(const ulonglong2*)(hb + i * 256 + kq * 4);
                fma2(acc[i], wv.x, hv.x);
                fma2(acc[i], wv.y, hv.y);
            }
        }
        #pragma unroll
        for (int i = 0; i < 10; ++i) rb[i * PR + r] = sum2(acc[i]);
        __syncthreads();

        if (tid < 320) {
            int local = ((1 << t) - 1) + (leaf >> (4 - t));
            const float* xa = g_XGA + (tree * NNODES + local) * G4;
            const float* xb = g_XGB + (tree * NNODES + local) * G4;
            const float* rr = sR + lc * PR + dl;
            float gi = rr[0]  + rr[1600]      + rr[3200]      + rr[4800];
            float gf = rr[16] + rr[1600 + 16] + rr[3200 + 16] + rr[4800 + 16];
            float gg = rr[32] + rr[1600 + 32] + rr[3200 + 32] + rr[4800 + 32];
            float go = rr[48] + rr[1600 + 48] + rr[3200 + 48] + rr[4800 + 48];
            gi += xa[d]       + xb[d];
            gf += xa[256 + d] + xb[256 + d];
            gg += xa[512 + d] + xb[512 + d];
            go += xa[768 + d] + xb[768 + d];
            cst = sigf(gf) * cst + sigf(gi) * tanhf(gg);
            float h = sigf(go) * tanhf(cst);
            __stcg(&g_H[bout][c * 256 + d], h);
        }
        if (t < 4) cybar(cy, target);
    }
}

// ---------------------------------------------------------------------------
// Leaf index per (b, tree) row: ballot over 16-lane groups.
// ---------------------------------------------------------------------------
__global__ void leaf_kernel(const float* __restrict__ cross) {
    int gid = blockIdx.x * 256 + threadIdx.x;
    float v = cross[gid];
    unsigned m = __ballot_sync(0xffffffffu, v > 0.5f);
    int lane = threadIdx.x & 31;
    unsigned m16 = (m >> (lane & 16)) & 0xFFFFu;
    if ((lane & 15) == 0) g_leaf[gid >> 4] = __ffs(m16) - 1;
}

// ---------------------------------------------------------------------------
// Gather: one thread per output float4.
// ---------------------------------------------------------------------------
__global__ void gather_kernel(float4* __restrict__ out) {
    int gid = blockIdx.x * 256 + threadIdx.x;
    int row = gid >> 6, q = gid & 63;
    int lf = g_leaf[row];
    int tr = row - (row / NT) * NT;
    const float4* H4 = (const float4*)g_H[0];
    out[gid] = __ldg(H4 + ((tr << 4) + lf) * 64 + q);
}

// ---------------------------------------------------------------------------
extern "C" void kernel_launch(void* const* d_in, const int* in_sizes, int n_in,
                              void* d_out, int out_size) {
    const float* cross = (const float*)d_in[0];
    const float* emb   = (const float*)d_in[1];
    const float* W_ih  = (const float*)d_in[2];
    const float* W_hh  = (const float*)d_in[3];
    const float* b_ih  = (const float*)d_in[4];
    const float* b_hh  = (const float*)d_in[5];

    static int attr_done = 0;
    if (!attr_done) {
        cudaFuncSetAttribute(lstm_kernel,
                             cudaFuncAttributeMaxDynamicSharedMemorySize,
                             SMEM_BYTES);
        attr_done = 1;
    }

    xg_kernel<<<dim3(8, 10, 2), 256>>>(emb, W_ih, b_ih, b_hh);
    leaf_kernel<<<BB * NT * NL / 256, 256>>>(cross);
    lstm_kernel<<<dim3(16, 8), NTHR, SMEM_BYTES>>>(W_hh);
    gather_kernel<<<BB * NT * 64 / 256, 256>>>((float4*)d_out);
}

// round 8
// speedup vs baseline: 1.3716x; 1.0354x over previous
#include <cuda_runtime.h>
#include <math.h>

typedef unsigned long long ull;

#define NT 10
#define NL 16
#define NNODES 31
#define BB 4096
#define G4 1024
#define NTHR 512

// lstm smem layout in floats (R4-proven)
#define PW 260                       // W row pitch (16B aligned, conflict-free)
#define PR 80                        // sR combo pitch
#define OFF_W 0                      // 64 rows x PW
#define OFF_H (64 * PW)              // 20 combos x 256
#define OFF_R (OFF_H + 20 * 256)     // 4 kslices x 20 combos x PR
#define SMEM_FLOATS (OFF_R + 4 * 20 * PR)
#define SMEM_BYTES (SMEM_FLOATS * 4)

__device__ __align__(16) float g_XGA[310 * G4];   // k-half 0 (+bias)
__device__ __align__(16) float g_XGB[310 * G4];   // k-half 1
__device__ __align__(16) float g_H[2][160 * 256];
__device__ int g_leaf[BB * NT];
__device__ unsigned g_cnt[8 * 32];
__device__ unsigned g_gen[8 * 32];

__device__ __forceinline__ float sigf(float x) { return 1.0f / (1.0f + __expf(-x)); }

__device__ __forceinline__ void fma2(ull& d, ull a, ull b) {
    asm("fma.rn.f32x2 %0, %1, %2, %0;" : "+l"(d) : "l"(a), "l"(b));
}
__device__ __forceinline__ float sum2(ull v) {
    float2 f = *(float2*)&v;
    return f.x + f.y;
}

__device__ __forceinline__ unsigned atom_add_release(unsigned* p, unsigned v) {
    unsigned r;
    asm volatile("atom.release.gpu.global.add.u32 %0, [%1], %2;"
                 : "=r"(r) : "l"(p), "r"(v) : "memory");
    return r;
}
__device__ __forceinline__ unsigned ld_acquire(unsigned* p) {
    unsigned r;
    asm volatile("ld.acquire.gpu.global.u32 %0, [%1];"
                 : "=r"(r) : "l"(p) : "memory");
    return r;
}
__device__ __forceinline__ void st_relaxed(unsigned* p, unsigned v) {
    asm volatile("st.relaxed.gpu.global.u32 [%0], %1;"
                 :: "l"(p), "r"(v) : "memory");
}

// Fence-free barrier across the 16 dx-blocks sharing one cy (all resident).
// Arrive: release-atomic (orders prior stcg stores). Wait: acquire-load poll.
__device__ __forceinline__ void cybar(int cy, unsigned& target) {
    __syncthreads();
    if (threadIdx.x == 0) {
        target += 1;
        unsigned old = atom_add_release(&g_cnt[cy * 32], 1);
        if (old == 15) {
            st_relaxed(&g_cnt[cy * 32], 0);          // ordered before gen bump
            atom_add_release(&g_gen[cy * 32], 1);    // by the release below
        } else {
            while ((int)(ld_acquire(&g_gen[cy * 32]) - target) < 0) {}
        }
    }
    __syncthreads();
}

// ---------------------------------------------------------------------------
// xg: XG[m][j] = emb[m] . W_ih[j] (+ bias on kz=0), K-split in 2 halves.
// Grid (8 colblk x 10 nodeblk x 2 ksplit), 256 thr.
// ---------------------------------------------------------------------------
#define PE 66          // sE pitch
#define PWX 132        // sW pitch (k-major rows)
__global__ void __launch_bounds__(256)
xg_kernel(const float* __restrict__ emb,
          const float* __restrict__ W_ih,
          const float* __restrict__ b_ih,
          const float* __restrict__ b_hh) {
    __shared__ float sE[32 * PE];        // 32 nodes x 64 k
    __shared__ float sW[64 * PWX];       // 64 k x 128 cols
    const int tid = threadIdx.x;
    const int cb = blockIdx.x;
    const int mb = blockIdx.y;
    const int kz = blockIdx.z;
    const int ty = tid >> 5, tx = tid & 31;

    float acc[4][4] = {};

    #pragma unroll
    for (int kc = 0; kc < 2; ++kc) {
        const int k0 = kz * 128 + kc * 64;
        for (int idx = tid; idx < 512; idx += 256) {
            int r = idx >> 4, q = idx & 15;
            int m = mb * 32 + r;
            float4 v = (m < 310)
                     ? *(const float4*)(emb + m * 256 + k0 + q * 4)
                     : make_float4(0.f, 0.f, 0.f, 0.f);
            sE[r * PE + q*4+0] = v.x; sE[r * PE + q*4+1] = v.y;
            sE[r * PE + q*4+2] = v.z; sE[r * PE + q*4+3] = v.w;
        }
        for (int idx = tid; idx < 2048; idx += 256) {
            int cl = idx >> 4, q = idx & 15;
            float4 v = *(const float4*)(W_ih + (cb * 128 + cl) * 256 + k0 + q * 4);
            sW[(q*4+0) * PWX + cl] = v.x;
            sW[(q*4+1) * PWX + cl] = v.y;
            sW[(q*4+2) * PWX + cl] = v.z;
            sW[(q*4+3) * PWX + cl] = v.w;
        }
        __syncthreads();
        #pragma unroll
        for (int k = 0; k < 64; ++k) {
            float e0 = sE[(ty*4+0) * PE + k];
            float e1 = sE[(ty*4+1) * PE + k];
            float e2 = sE[(ty*4+2) * PE + k];
            float e3 = sE[(ty*4+3) * PE + k];
            float w0 = sW[k * PWX + tx];
            float w1 = sW[k * PWX + tx + 32];
            float w2 = sW[k * PWX + tx + 64];
            float w3 = sW[k * PWX + tx + 96];
            acc[0][0] += e0*w0; acc[0][1] += e0*w1; acc[0][2] += e0*w2; acc[0][3] += e0*w3;
            acc[1][0] += e1*w0; acc[1][1] += e1*w1; acc[1][2] += e1*w2; acc[1][3] += e1*w3;
            acc[2][0] += e2*w0; acc[2][1] += e2*w1; acc[2][2] += e2*w2; acc[2][3] += e2*w3;
            acc[3][0] += e3*w0; acc[3][1] += e3*w1; acc[3][2] += e3*w2; acc[3][3] += e3*w3;
        }
        __syncthreads();
    }

    float* dst = kz ? g_XGB : g_XGA;
    #pragma unroll
    for (int i = 0; i < 4; ++i) {
        int m = mb * 32 + ty * 4 + i;
        if (m >= 310) break;
        #pragma unroll
        for (int j = 0; j < 4; ++j) {
            int col = cb * 128 + tx + 32 * j;
            float v = acc[i][j];
            if (kz == 0) v += b_ih[col] + b_hh[col];
            dst[m * G4 + col] = v;
        }
    }
}

// ---------------------------------------------------------------------------
// Persistent LSTM. Grid (16,8), 512 thr, 1 block/SM. XG prefetched at step
// top (off the critical path); fence-free barrier between steps.
// ---------------------------------------------------------------------------
__global__ void __launch_bounds__(NTHR, 1)
lstm_kernel(const float* __restrict__ W_hh) {
    extern __shared__ __align__(16) float sm[];
    float* sW = sm + OFF_W;
    float* sh = sm + OFF_H;
    float* sR = sm + OFF_R;

    const int tid = threadIdx.x;
    const int dx = blockIdx.x;      // 0..15
    const int cy = blockIdx.y;      // 0..7
    const int d0 = dx << 4;

    unsigned target = 0;
    if (tid == 0) target = ld_acquire(&g_gen[cy * 32]);

    // Cache W_hh slice: row r: j = (r>>4)*256 + d0 + (r&15), k = 0..255.
    for (int i = tid; i < 4096; i += NTHR) {
        int row = i >> 6, q = i & 63;
        int j = ((row >> 4) << 8) + d0 + (row & 15);
        *(float4*)(sW + row * PW + q * 4) = ((const float4*)W_hh)[j * 64 + q];
    }

    const int lc = tid >> 4, dl = tid & 15;
    const int c = cy * 20 + lc;
    const int d = d0 + dl;
    const int tree = c >> 4, leaf = c & 15;

    // ---- Step 0 (h0 = c0 = 0) ----
    float cst = 0.f;
    if (tid < 320) {
        const float* xa = g_XGA + (tree * NNODES) * G4;
        const float* xb = g_XGB + (tree * NNODES) * G4;
        float gi = __ldg(xa + d)       + __ldg(xb + d);
        float gg = __ldg(xa + 512 + d) + __ldg(xb + 512 + d);
        float go = __ldg(xa + 768 + d) + __ldg(xb + 768 + d);
        cst = sigf(gi) * tanhf(gg);
        float h = sigf(go) * tanhf(cst);
        __stcg(&g_H[0][c * 256 + d], h);
    }
    cybar(cy, target);

    const int w = tid >> 5, lane = tid & 31;
    const int rg = w & 1;
    const int cs = (w >> 1) & 1;
    const int ks = w >> 2;
    const int r = rg * 32 + lane;
    const float* Wr = sW + r * PW + ks * 64;
    const float* hb = sh + cs * 10 * 256 + ks * 64;
    float* rb = sR + ks * (20 * PR) + cs * 10 * PR;

    #pragma unroll
    for (int t = 1; t <= 4; ++t) {
        const int bin = 1 - (t & 1), bout = t & 1;

        // Prefetch this step's XG contribution (independent of h).
        float pa0 = 0.f, pa1 = 0.f, pa2 = 0.f, pa3 = 0.f;
        if (tid < 320) {
            int local = ((1 << t) - 1) + (leaf >> (4 - t));
            const float* xa = g_XGA + (tree * NNODES + local) * G4;
            const float* xb = g_XGB + (tree * NNODES + local) * G4;
            pa0 = __ldg(xa + d)       + __ldg(xb + d);
            pa1 = __ldg(xa + 256 + d) + __ldg(xb + 256 + d);
            pa2 = __ldg(xa + 512 + d) + __ldg(xb + 512 + d);
            pa3 = __ldg(xa + 768 + d) + __ldg(xb + 768 + d);
        }

        // Load h tile (20 x 256) from L2.
        {
            const float4* src = (const float4*)(g_H[bin] + cy * 5120);
            float4* dst = (float4*)sh;
            for (int i = tid; i < 1280; i += NTHR) dst[i] = __ldcg(src + i);
        }
        __syncthreads();

        ull acc[10] = {};
        #pragma unroll
        for (int kq = 0; kq < 16; ++kq) {
            ulonglong2 wv = *(const ulonglong2*)(Wr + kq * 4);
            #pragma unroll
            for (int i = 0; i < 10; ++i) {
                ulonglong2 hv = *(const ulonglong2*)(hb + i * 256 + kq * 4);
                fma2(acc[i], wv.x, hv.x);
                fma2(acc[i], wv.y, hv.y);
            }
        }
        #pragma unroll
        for (int i = 0; i < 10; ++i) rb[i * PR + r] = sum2(acc[i]);
        __syncthreads();

        if (tid < 320) {
            const float* rr = sR + lc * PR + dl;
            float gi = rr[0]  + rr[1600]      + rr[3200]      + rr[4800];
            float gf = rr[16] + rr[1600 + 16] + rr[3200 + 16] + rr[4800 + 16];
            float gg = rr[32] + rr[1600 + 32] + rr[3200 + 32] + rr[4800 + 32];
            float go = rr[48] + rr[1600 + 48] + rr[3200 + 48] + rr[4800 + 48];
            gi += pa0; gf += pa1; gg += pa2; go += pa3;
            cst = sigf(gf) * cst + sigf(gi) * tanhf(gg);
            float h = sigf(go) * tanhf(cst);
            __stcg(&g_H[bout][c * 256 + d], h);
        }
        if (t < 4) cybar(cy, target);
    }
}

// ---------------------------------------------------------------------------
// Leaf index per (b, tree) row: ballot over 16-lane groups.
// ---------------------------------------------------------------------------
__global__ void leaf_kernel(const float* __restrict__ cross) {
    int gid = blockIdx.x * 256 + threadIdx.x;
    float v = cross[gid];
    unsigned m = __ballot_sync(0xffffffffu, v > 0.5f);
    int lane = threadIdx.x & 31;
    unsigned m16 = (m >> (lane & 16)) & 0xFFFFu;
    if ((lane & 15) == 0) g_leaf[gid >> 4] = __ffs(m16) - 1;
}

// ---------------------------------------------------------------------------
// Gather: two output float4 per thread (rows 20480 apart -> coalescing
// preserved, MLP x2, index math amortized).
// ---------------------------------------------------------------------------
__global__ void gather_kernel(float4* __restrict__ out) {
    int gid = blockIdx.x * 256 + threadIdx.x;     // 0..1310719
    int row0 = gid >> 6, q = gid & 63;
    int row1 = row0 + 20480;
    int lf0 = g_leaf[row0];
    int lf1 = g_leaf[row1];
    int tr0 = row0 - (row0 / NT) * NT;
    int tr1 = row1 - (row1 / NT) * NT;
    const float4* H4 = (const float4*)g_H[0];
    float4 v0 = __ldg(H4 + ((tr0 << 4) + lf0) * 64 + q);
    float4 v1 = __ldg(H4 + ((tr1 << 4) + lf1) * 64 + q);
    out[(size_t)row0 * 64 + q] = v0;
    out[(size_t)row1 * 64 + q] = v1;
}

// ---------------------------------------------------------------------------
extern "C" void kernel_launch(void* const* d_in, const int* in_sizes, int n_in,
                              void* d_out, int out_size) {
    const float* cross = (const float*)d_in[0];
    const float* emb   = (const float*)d_in[1];
    const float* W_ih  = (const float*)d_in[2];
    const float* W_hh  = (const float*)d_in[3];
    const float* b_ih  = (const float*)d_in[4];
    const float* b_hh  = (const float*)d_in[5];

    static int attr_done = 0;
    if (!attr_done) {
        cudaFuncSetAttribute(lstm_kernel,
                             cudaFuncAttributeMaxDynamicSharedMemorySize,
                             SMEM_BYTES);
        attr_done = 1;
    }

    xg_kernel<<<dim3(8, 10, 2), 256>>>(emb, W_ih, b_ih, b_hh);
    leaf_kernel<<<BB * NT * NL / 256, 256>>>(cross);
    lstm_kernel<<<dim3(16, 8), NTHR, SMEM_BYTES>>>(W_hh);
    gather_kernel<<<BB * NT * 64 / 512, 256>>>((float4*)d_out);
}

// round 9
// speedup vs baseline: 1.4797x; 1.0788x over previous
#include <cuda_runtime.h>
#include <math.h>

typedef unsigned long long ull;

#define NT 10
#define NL 16
#define NNODES 31
#define BB 4096
#define G4 1024
#define NTHR 512

// lstm smem layout in floats (R4-proven)
#define PW 260                       // W row pitch (16B aligned, conflict-free)
#define PR 80                        // sR combo pitch
#define OFF_W 0                      // 64 rows x PW
#define OFF_H (64 * PW)              // 20 combos x 256
#define OFF_R (OFF_H + 20 * 256)     // 4 kslices x 20 combos x PR
#define SMEM_FLOATS (OFF_R + 4 * 20 * PR)
#define SMEM_BYTES (SMEM_FLOATS * 4)

__device__ __align__(16) float g_XGA[310 * G4];   // k-half 0 (+bias)
__device__ __align__(16) float g_XGB[310 * G4];   // k-half 1
__device__ __align__(16) float g_H[2][160 * 256];
__device__ int g_leaf[BB * NT];
__device__ unsigned g_cnt[8 * 32];
__device__ unsigned g_gen[8 * 32];

__device__ __forceinline__ float sigf(float x) { return 1.0f / (1.0f + __expf(-x)); }

__device__ __forceinline__ void fma2(ull& d, ull a, ull b) {
    asm("fma.rn.f32x2 %0, %1, %2, %0;" : "+l"(d) : "l"(a), "l"(b));
}
__device__ __forceinline__ float sum2(ull v) {
    float2 f = *(float2*)&v;
    return f.x + f.y;
}

__device__ __forceinline__ unsigned atom_add_release(unsigned* p, unsigned v) {
    unsigned r;
    asm volatile("atom.release.gpu.global.add.u32 %0, [%1], %2;"
                 : "=r"(r) : "l"(p), "r"(v) : "memory");
    return r;
}
__device__ __forceinline__ unsigned ld_acquire(unsigned* p) {
    unsigned r;
    asm volatile("ld.acquire.gpu.global.u32 %0, [%1];"
                 : "=r"(r) : "l"(p) : "memory");
    return r;
}
__device__ __forceinline__ void st_relaxed(unsigned* p, unsigned v) {
    asm volatile("st.relaxed.gpu.global.u32 [%0], %1;"
                 :: "l"(p), "r"(v) : "memory");
}

// Fence-free barrier across the 16 dx-blocks sharing one cy (all resident).
__device__ __forceinline__ void cybar(int cy, unsigned& target) {
    __syncthreads();
    if (threadIdx.x == 0) {
        target += 1;
        unsigned old = atom_add_release(&g_cnt[cy * 32], 1);
        if (old == 15) {
            st_relaxed(&g_cnt[cy * 32], 0);
            atom_add_release(&g_gen[cy * 32], 1);
        } else {
            while ((int)(ld_acquire(&g_gen[cy * 32]) - target) < 0) {}
        }
    }
    __syncthreads();
}

// ---------------------------------------------------------------------------
// xg: XG[m][j] = emb[m] . W_ih[j] (+ bias on kz=0), K-split in 2 halves.
// Grid (8 colblk x 10 nodeblk x 2 ksplit), 256 thr.
// PWX=129: transpose-store bank = (4q+j+cl) mod 32 -> 2-way (was 16-way at
// PWX=132); compute reads k*129+tx stay conflict-free (consecutive lanes).
// ---------------------------------------------------------------------------
#define PE 66          // sE pitch
#define PWX 129        // sW pitch (k-major rows)
__global__ void __launch_bounds__(256)
xg_kernel(const float* __restrict__ emb,
          const float* __restrict__ W_ih,
          const float* __restrict__ b_ih,
          const float* __restrict__ b_hh) {
    __shared__ float sE[32 * PE];        // 32 nodes x 64 k
    __shared__ float sW[64 * PWX];       // 64 k x 128 cols
    const int tid = threadIdx.x;
    const int cb = blockIdx.x;
    const int mb = blockIdx.y;
    const int kz = blockIdx.z;
    const int ty = tid >> 5, tx = tid & 31;

    float acc[4][4] = {};

    #pragma unroll
    for (int kc = 0; kc < 2; ++kc) {
        const int k0 = kz * 128 + kc * 64;
        for (int idx = tid; idx < 512; idx += 256) {
            int r = idx >> 4, q = idx & 15;
            int m = mb * 32 + r;
            float4 v = (m < 310)
                     ? *(const float4*)(emb + m * 256 + k0 + q * 4)
                     : make_float4(0.f, 0.f, 0.f, 0.f);
            sE[r * PE + q*4+0] = v.x; sE[r * PE + q*4+1] = v.y;
            sE[r * PE + q*4+2] = v.z; sE[r * PE + q*4+3] = v.w;
        }
        for (int idx = tid; idx < 2048; idx += 256) {
            int cl = idx >> 4, q = idx & 15;
            float4 v = *(const float4*)(W_ih + (cb * 128 + cl) * 256 + k0 + q * 4);
            sW[(q*4+0) * PWX + cl] = v.x;
            sW[(q*4+1) * PWX + cl] = v.y;
            sW[(q*4+2) * PWX + cl] = v.z;
            sW[(q*4+3) * PWX + cl] = v.w;
        }
        __syncthreads();
        #pragma unroll
        for (int k = 0; k < 64; ++k) {
            float e0 = sE[(ty*4+0) * PE + k];
            float e1 = sE[(ty*4+1) * PE + k];
            float e2 = sE[(ty*4+2) * PE + k];
            float e3 = sE[(ty*4+3) * PE + k];
            float w0 = sW[k * PWX + tx];
            float w1 = sW[k * PWX + tx + 32];
            float w2 = sW[k * PWX + tx + 64];
            float w3 = sW[k * PWX + tx + 96];
            acc[0][0] += e0*w0; acc[0][1] += e0*w1; acc[0][2] += e0*w2; acc[0][3] += e0*w3;
            acc[1][0] += e1*w0; acc[1][1] += e1*w1; acc[1][2] += e1*w2; acc[1][3] += e1*w3;
            acc[2][0] += e2*w0; acc[2][1] += e2*w1; acc[2][2] += e2*w2; acc[2][3] += e2*w3;
            acc[3][0] += e3*w0; acc[3][1] += e3*w1; acc[3][2] += e3*w2; acc[3][3] += e3*w3;
        }
        __syncthreads();
    }

    float* dst = kz ? g_XGB : g_XGA;
    #pragma unroll
    for (int i = 0; i < 4; ++i) {
        int m = mb * 32 + ty * 4 + i;
        if (m >= 310) break;
        #pragma unroll
        for (int j = 0; j < 4; ++j) {
            int col = cb * 128 + tx + 32 * j;
            float v = acc[i][j];
            if (kz == 0) v += b_ih[col] + b_hh[col];
            dst[m * G4 + col] = v;
        }
    }
}

// ---------------------------------------------------------------------------
// Persistent LSTM. Grid (16,8), 512 thr, 1 block/SM. XG prefetched at step
// top; fence-free barrier between steps.
// ---------------------------------------------------------------------------
__global__ void __launch_bounds__(NTHR, 1)
lstm_kernel(const float* __restrict__ W_hh) {
    extern __shared__ __align__(16) float sm[];
    float* sW = sm + OFF_W;
    float* sh = sm + OFF_H;
    float* sR = sm + OFF_R;

    const int tid = threadIdx.x;
    const int dx = blockIdx.x;      // 0..15
    const int cy = blockIdx.y;      // 0..7
    const int d0 = dx << 4;

    unsigned target = 0;
    if (tid == 0) target = ld_acquire(&g_gen[cy * 32]);

    for (int i = tid; i < 4096; i += NTHR) {
        int row = i >> 6, q = i & 63;
        int j = ((row >> 4) << 8) + d0 + (row & 15);
        *(float4*)(sW + row * PW + q * 4) = ((const float4*)W_hh)[j * 64 + q];
    }

    const int lc = tid >> 4, dl = tid & 15;
    const int c = cy * 20 + lc;
    const int d = d0 + dl;
    const int tree = c >> 4, leaf = c & 15;

    // ---- Step 0 (h0 = c0 = 0) ----
    float cst = 0.f;
    if (tid < 320) {
        const float* xa = g_XGA + (tree * NNODES) * G4;
        const float* xb = g_XGB + (tree * NNODES) * G4;
        float gi = __ldg(xa + d)       + __ldg(xb + d);
        float gg = __ldg(xa + 512 + d) + __ldg(xb + 512 + d);
        float go = __ldg(xa + 768 + d) + __ldg(xb + 768 + d);
        cst = sigf(gi) * tanhf(gg);
        float h = sigf(go) * tanhf(cst);
        __stcg(&g_H[0][c * 256 + d], h);
    }
    cybar(cy, target);

    const int w = tid >> 5, lane = tid & 31;
    const int rg = w & 1;
    const int cs = (w >> 1) & 1;
    const int ks = w >> 2;
    const int r = rg * 32 + lane;
    const float* Wr = sW + r * PW + ks * 64;
    const float* hb = sh + cs * 10 * 256 + ks * 64;
    float* rb = sR + ks * (20 * PR) + cs * 10 * PR;

    #pragma unroll
    for (int t = 1; t <= 4; ++t) {
        const int bin = 1 - (t & 1), bout = t & 1;

        float pa0 = 0.f, pa1 = 0.f, pa2 = 0.f, pa3 = 0.f;
        if (tid < 320) {
            int local = ((1 << t) - 1) + (leaf >> (4 - t));
            const float* xa = g_XGA + (tree * NNODES + local) * G4;
            const float* xb = g_XGB + (tree * NNODES + local) * G4;
            pa0 = __ldg(xa + d)       + __ldg(xb + d);
            pa1 = __ldg(xa + 256 + d) + __ldg(xb + 256 + d);
            pa2 = __ldg(xa + 512 + d) + __ldg(xb + 512 + d);
            pa3 = __ldg(xa + 768 + d) + __ldg(xb + 768 + d);
        }

        {
            const float4* src = (const float4*)(g_H[bin] + cy * 5120);
            float4* dst = (float4*)sh;
            for (int i = tid; i < 1280; i += NTHR) dst[i] = __ldcg(src + i);
        }
        __syncthreads();

        ull acc[10] = {};
        #pragma unroll
        for (int kq = 0; kq < 16; ++kq) {
            ulonglong2 wv = *(const ulonglong2*)(Wr + kq * 4);
            #pragma unroll
            for (int i = 0; i < 10; ++i) {
                ulonglong2 hv = *(const ulonglong2*)(hb + i * 256 + kq * 4);
                fma2(acc[i], wv.x, hv.x);
                fma2(acc[i], wv.y, hv.y);
            }
        }
        #pragma unroll
        for (int i = 0; i < 10; ++i) rb[i * PR + r] = sum2(acc[i]);
        __syncthreads();

        if (tid < 320) {
            const float* rr = sR + lc * PR + dl;
            float gi = rr[0]  + rr[1600]      + rr[3200]      + rr[4800];
            float gf = rr[16] + rr[1600 + 16] + rr[3200 + 16] + rr[4800 + 16];
            float gg = rr[32] + rr[1600 + 32] + rr[3200 + 32] + rr[4800 + 32];
            float go = rr[48] + rr[1600 + 48] + rr[3200 + 48] + rr[4800 + 48];
            gi += pa0; gf += pa1; gg += pa2; go += pa3;
            cst = sigf(gf) * cst + sigf(gi) * tanhf(gg);
            float h = sigf(go) * tanhf(cst);
            __stcg(&g_H[bout][c * 256 + d], h);
        }
        if (t < 4) cybar(cy, target);
    }
}

// ---------------------------------------------------------------------------
// Leaf index per (b, tree) row: ballot over 16-lane groups.
// ---------------------------------------------------------------------------
__global__ void leaf_kernel(const float* __restrict__ cross) {
    int gid = blockIdx.x * 256 + threadIdx.x;
    float v = cross[gid];
    unsigned m = __ballot_sync(0xffffffffu, v > 0.5f);
    int lane = threadIdx.x & 31;
    unsigned m16 = (m >> (lane & 16)) & 0xFFFFu;
    if ((lane & 15) == 0) g_leaf[gid >> 4] = __ffs(m16) - 1;
}

// ---------------------------------------------------------------------------
// Gather: two output float4 per thread (rows 20480 apart).
// ---------------------------------------------------------------------------
__global__ void gather_kernel(float4* __restrict__ out) {
    int gid = blockIdx.x * 256 + threadIdx.x;     // 0..1310719
    int row0 = gid >> 6, q = gid & 63;
    int row1 = row0 + 20480;
    int lf0 = g_leaf[row0];
    int lf1 = g_leaf[row1];
    int tr0 = row0 - (row0 / NT) * NT;
    int tr1 = row1 - (row1 / NT) * NT;
    const float4* H4 = (const float4*)g_H[0];
    float4 v0 = __ldg(H4 + ((tr0 << 4) + lf0) * 64 + q);
    float4 v1 = __ldg(H4 + ((tr1 << 4) + lf1) * 64 + q);
    out[(size_t)row0 * 64 + q] = v0;
    out[(size_t)row1 * 64 + q] = v1;
}

// ---------------------------------------------------------------------------
extern "C" void kernel_launch(void* const* d_in, const int* in_sizes, int n_in,
                              void* d_out, int out_size) {
    const float* cross = (const float*)d_in[0];
    const float* emb   = (const float*)d_in[1];
    const float* W_ih  = (const float*)d_in[2];
    const float* W_hh  = (const float*)d_in[3];
    const float* b_ih  = (const float*)d_in[4];
    const float* b_hh  = (const float*)d_in[5];

    static int attr_done = 0;
    if (!attr_done) {
        cudaFuncSetAttribute(lstm_kernel,
                             cudaFuncAttributeMaxDynamicSharedMemorySize,
                             SMEM_BYTES);
        attr_done = 1;
    }

    xg_kernel<<<dim3(8, 10, 2), 256>>>(emb, W_ih, b_ih, b_hh);
    leaf_kernel<<<BB * NT * NL / 256, 256>>>(cross);
    lstm_kernel<<<dim3(16, 8), NTHR, SMEM_BYTES>>>(W_hh);
    gather_kernel<<<BB * NT * 64 / 512, 256>>>((float4*)d_out);
}

// round 10
// speedup vs baseline: 1.5404x; 1.0410x over previous
#include <cuda_runtime.h>
#include <math.h>

typedef unsigned long long ull;

#define NT 10
#define NL 16
#define NNODES 31
#define BB 4096
#define G4 1024
#define NTHR 512

// lstm smem layout in floats
#define PW 260                       // W row pitch (16B aligned, conflict-free)
#define PR 80                        // sR combo pitch
#define OFF_W 0                      // 64 rows x PW
#define OFF_H (64 * PW)              // 20 combos x 256
#define OFF_R (OFF_H + 20 * 256)     // 8 kslices x 20 combos x PR
#define SMEM_FLOATS (OFF_R + 8 * 20 * PR)
#define SMEM_BYTES (SMEM_FLOATS * 4)

__device__ __align__(16) float g_XGA[310 * G4];   // k-half 0 (+bias)
__device__ __align__(16) float g_XGB[310 * G4];   // k-half 1
__device__ __align__(16) float g_H[2][160 * 256];
__device__ int g_leaf[BB * NT];
__device__ unsigned g_cnt[8 * 32];
__device__ unsigned g_gen[8 * 32];

__device__ __forceinline__ float sigf(float x) { return 1.0f / (1.0f + __expf(-x)); }

__device__ __forceinline__ void fma2(ull& d, ull a, ull b) {
    asm("fma.rn.f32x2 %0, %1, %2, %0;" : "+l"(d) : "l"(a), "l"(b));
}
__device__ __forceinline__ float sum2(ull v) {
    float2 f = *(float2*)&v;
    return f.x + f.y;
}

__device__ __forceinline__ unsigned atom_add_release(unsigned* p, unsigned v) {
    unsigned r;
    asm volatile("atom.release.gpu.global.add.u32 %0, [%1], %2;"
                 : "=r"(r) : "l"(p), "r"(v) : "memory");
    return r;
}
__device__ __forceinline__ unsigned ld_acquire(unsigned* p) {
    unsigned r;
    asm volatile("ld.acquire.gpu.global.u32 %0, [%1];"
                 : "=r"(r) : "l"(p) : "memory");
    return r;
}
__device__ __forceinline__ void st_relaxed(unsigned* p, unsigned v) {
    asm volatile("st.relaxed.gpu.global.u32 [%0], %1;"
                 :: "l"(p), "r"(v) : "memory");
}

// Fence-free barrier across the 16 dx-blocks sharing one cy (all resident).
__device__ __forceinline__ void cybar(int cy, unsigned& target) {
    __syncthreads();
    if (threadIdx.x == 0) {
        target += 1;
        unsigned old = atom_add_release(&g_cnt[cy * 32], 1);
        if (old == 15) {
            st_relaxed(&g_cnt[cy * 32], 0);
            atom_add_release(&g_gen[cy * 32], 1);
        } else {
            while ((int)(ld_acquire(&g_gen[cy * 32]) - target) < 0) {}
        }
    }
    __syncthreads();
}

// ---------------------------------------------------------------------------
// xg: XG[m][j] = emb[m] . W_ih[j] (+ bias on kz=0), K-split in 2 halves.
// Grid (8 colblk x 10 nodeblk x 2 ksplit), 256 thr. (R9-proven)
// ---------------------------------------------------------------------------
#define PE 66          // sE pitch
#define PWX 129        // sW pitch (k-major rows)
__global__ void __launch_bounds__(256)
xg_kernel(const float* __restrict__ emb,
          const float* __restrict__ W_ih,
          const float* __restrict__ b_ih,
          const float* __restrict__ b_hh) {
    __shared__ float sE[32 * PE];        // 32 nodes x 64 k
    __shared__ float sW[64 * PWX];       // 64 k x 128 cols
    const int tid = threadIdx.x;
    const int cb = blockIdx.x;
    const int mb = blockIdx.y;
    const int kz = blockIdx.z;
    const int ty = tid >> 5, tx = tid & 31;

    float acc[4][4] = {};

    #pragma unroll
    for (int kc = 0; kc < 2; ++kc) {
        const int k0 = kz * 128 + kc * 64;
        for (int idx = tid; idx < 512; idx += 256) {
            int r = idx >> 4, q = idx & 15;
            int m = mb * 32 + r;
            float4 v = (m < 310)
                     ? *(const float4*)(emb + m * 256 + k0 + q * 4)
                     : make_float4(0.f, 0.f, 0.f, 0.f);
            sE[r * PE + q*4+0] = v.x; sE[r * PE + q*4+1] = v.y;
            sE[r * PE + q*4+2] = v.z; sE[r * PE + q*4+3] = v.w;
        }
        for (int idx = tid; idx < 2048; idx += 256) {
            int cl = idx >> 4, q = idx & 15;
            float4 v = *(const float4*)(W_ih + (cb * 128 + cl) * 256 + k0 + q * 4);
            sW[(q*4+0) * PWX + cl] = v.x;
            sW[(q*4+1) * PWX + cl] = v.y;
            sW[(q*4+2) * PWX + cl] = v.z;
            sW[(q*4+3) * PWX + cl] = v.w;
        }
        __syncthreads();
        #pragma unroll
        for (int k = 0; k < 64; ++k) {
            float e0 = sE[(ty*4+0) * PE + k];
            float e1 = sE[(ty*4+1) * PE + k];
            float e2 = sE[(ty*4+2) * PE + k];
            float e3 = sE[(ty*4+3) * PE + k];
            float w0 = sW[k * PWX + tx];
            float w1 = sW[k * PWX + tx + 32];
            float w2 = sW[k * PWX + tx + 64];
            float w3 = sW[k * PWX + tx + 96];
            acc[0][0] += e0*w0; acc[0][1] += e0*w1; acc[0][2] += e0*w2; acc[0][3] += e0*w3;
            acc[1][0] += e1*w0; acc[1][1] += e1*w1; acc[1][2] += e1*w2; acc[1][3] += e1*w3;
            acc[2][0] += e2*w0; acc[2][1] += e2*w1; acc[2][2] += e2*w2; acc[2][3] += e2*w3;
            acc[3][0] += e3*w0; acc[3][1] += e3*w1; acc[3][2] += e3*w2; acc[3][3] += e3*w3;
        }
        __syncthreads();
    }

    float* dst = kz ? g_XGB : g_XGA;
    #pragma unroll
    for (int i = 0; i < 4; ++i) {
        int m = mb * 32 + ty * 4 + i;
        if (m >= 310) break;
        #pragma unroll
        for (int j = 0; j < 4; ++j) {
            int col = cb * 128 + tx + 32 * j;
            float v = acc[i][j];
            if (kz == 0) v += b_ih[col] + b_hh[col];
            dst[m * G4 + col] = v;
        }
    }
}

// ---------------------------------------------------------------------------
// Persistent LSTM. Grid (16,8), 512 thr, 1 block/SM.
// Warp tile now 64 rows x 10 combos x 32k: warp (cs = w&1, ks = w>>1).
// Lane owns rows {lane, lane+32}; 8 K-partials summed in finalize.
// Cuts crossbar wavefronts/step 3584 -> ~2300 (h-broadcasts halved).
// ---------------------------------------------------------------------------
__global__ void __launch_bounds__(NTHR, 1)
lstm_kernel(const float* __restrict__ W_hh) {
    extern __shared__ __align__(16) float sm[];
    float* sW = sm + OFF_W;
    float* sh = sm + OFF_H;
    float* sR = sm + OFF_R;

    const int tid = threadIdx.x;
    const int dx = blockIdx.x;      // 0..15
    const int cy = blockIdx.y;      // 0..7
    const int d0 = dx << 4;

    unsigned target = 0;
    if (tid == 0) target = ld_acquire(&g_gen[cy * 32]);

    for (int i = tid; i < 4096; i += NTHR) {
        int row = i >> 6, q = i & 63;
        int j = ((row >> 4) << 8) + d0 + (row & 15);
        *(float4*)(sW + row * PW + q * 4) = ((const float4*)W_hh)[j * 64 + q];
    }

    const int lc = tid >> 4, dl = tid & 15;
    const int c = cy * 20 + lc;
    const int d = d0 + dl;
    const int tree = c >> 4, leaf = c & 15;

    // ---- Step 0 (h0 = c0 = 0) ----
    float cst = 0.f;
    if (tid < 320) {
        const float* xa = g_XGA + (tree * NNODES) * G4;
        const float* xb = g_XGB + (tree * NNODES) * G4;
        float gi = __ldg(xa + d)       + __ldg(xb + d);
        float gg = __ldg(xa + 512 + d) + __ldg(xb + 512 + d);
        float go = __ldg(xa + 768 + d) + __ldg(xb + 768 + d);
        cst = sigf(gi) * tanhf(gg);
        float h = sigf(go) * tanhf(cst);
        __stcg(&g_H[0][c * 256 + d], h);
    }
    cybar(cy, target);

    const int w = tid >> 5, lane = tid & 31;
    const int cs = w & 1;            // combo half: combos cs*10..+9
    const int ks = w >> 1;           // K slice: k = ks*32..+31 (8 slices)
    const float* Wra = sW + lane * PW + ks * 32;         // row = lane
    const float* Wrb = sW + (lane + 32) * PW + ks * 32;  // row = lane+32
    const float* hb = sh + cs * 10 * 256 + ks * 32;
    float* rb = sR + ks * (20 * PR) + cs * 10 * PR;

    #pragma unroll
    for (int t = 1; t <= 4; ++t) {
        const int bin = 1 - (t & 1), bout = t & 1;

        // Prefetch this step's XG contribution (independent of h).
        float pa0 = 0.f, pa1 = 0.f, pa2 = 0.f, pa3 = 0.f;
        if (tid < 320) {
            int local = ((1 << t) - 1) + (leaf >> (4 - t));
            const float* xa = g_XGA + (tree * NNODES + local) * G4;
            const float* xb = g_XGB + (tree * NNODES + local) * G4;
            pa0 = __ldg(xa + d)       + __ldg(xb + d);
            pa1 = __ldg(xa + 256 + d) + __ldg(xb + 256 + d);
            pa2 = __ldg(xa + 512 + d) + __ldg(xb + 512 + d);
            pa3 = __ldg(xa + 768 + d) + __ldg(xb + 768 + d);
        }

        // Load h tile (20 x 256) from L2.
        {
            const float4* src = (const float4*)(g_H[bin] + cy * 5120);
            float4* dst = (float4*)sh;
            for (int i = tid; i < 1280; i += NTHR) dst[i] = __ldcg(src + i);
        }
        __syncthreads();

        ull accA[10] = {};
        ull accB[10] = {};
        #pragma unroll
        for (int kq = 0; kq < 8; ++kq) {
            ulonglong2 wa = *(const ulonglong2*)(Wra + kq * 4);
            ulonglong2 wb = *(const ulonglong2*)(Wrb + kq * 4);
            #pragma unroll
            for (int i = 0; i < 10; ++i) {
                ulonglong2 hv = *(const ulonglong2*)(hb + i * 256 + kq * 4);
                fma2(accA[i], wa.x, hv.x); fma2(accA[i], wa.y, hv.y);
                fma2(accB[i], wb.x, hv.x); fma2(accB[i], wb.y, hv.y);
            }
        }
        #pragma unroll
        for (int i = 0; i < 10; ++i) {
            rb[i * PR + lane]      = sum2(accA[i]);
            rb[i * PR + lane + 32] = sum2(accB[i]);
        }
        __syncthreads();

        if (tid < 320) {
            const float* rr = sR + lc * PR + dl;
            float gi = pa0, gf = pa1, gg = pa2, go = pa3;
            #pragma unroll
            for (int kk = 0; kk < 8; ++kk) {
                gi += rr[kk * 1600 +  0];
                gf += rr[kk * 1600 + 16];
                gg += rr[kk * 1600 + 32];
                go += rr[kk * 1600 + 48];
            }
            cst = sigf(gf) * cst + sigf(gi) * tanhf(gg);
            float h = sigf(go) * tanhf(cst);
            __stcg(&g_H[bout][c * 256 + d], h);
        }
        if (t < 4) cybar(cy, target);
    }
}

// ---------------------------------------------------------------------------
// Leaf index per (b, tree) row: ballot over 16-lane groups.
// ---------------------------------------------------------------------------
__global__ void leaf_kernel(const float* __restrict__ cross) {
    int gid = blockIdx.x * 256 + threadIdx.x;
    float v = cross[gid];
    unsigned m = __ballot_sync(0xffffffffu, v > 0.5f);
    int lane = threadIdx.x & 31;
    unsigned m16 = (m >> (lane & 16)) & 0xFFFFu;
    if ((lane & 15) == 0) g_leaf[gid >> 4] = __ffs(m16) - 1;
}

// ---------------------------------------------------------------------------
// Gather: four output float4 per thread (rows 10240 apart -> coalescing
// preserved, MLP x4, index math amortized).
// ---------------------------------------------------------------------------
__global__ void gather_kernel(float4* __restrict__ out) {
    int gid = blockIdx.x * 256 + threadIdx.x;     // 0..655359
    int row0 = gid >> 6, q = gid & 63;
    const float4* H4 = (const float4*)g_H[0];
    #pragma unroll
    for (int j = 0; j < 4; ++j) {
        int row = row0 + j * 10240;
        int lf = g_leaf[row];
        int tr = row - (row / NT) * NT;
        out[(size_t)row * 64 + q] = __ldg(H4 + ((tr << 4) + lf) * 64 + q);
    }
}

// ---------------------------------------------------------------------------
extern "C" void kernel_launch(void* const* d_in, const int* in_sizes, int n_in,
                              void* d_out, int out_size) {
    const float* cross = (const float*)d_in[0];
    const float* emb   = (const float*)d_in[1];
    const float* W_ih  = (const float*)d_in[2];
    const float* W_hh  = (const float*)d_in[3];
    const float* b_ih  = (const float*)d_in[4];
    const float* b_hh  = (const float*)d_in[5];

    static int attr_done = 0;
    if (!attr_done) {
        cudaFuncSetAttribute(lstm_kernel,
                             cudaFuncAttributeMaxDynamicSharedMemorySize,
                             SMEM_BYTES);
        attr_done = 1;
    }

    xg_kernel<<<dim3(8, 10, 2), 256>>>(emb, W_ih, b_ih, b_hh);
    leaf_kernel<<<BB * NT * NL / 256, 256>>>(cross);
    lstm_kernel<<<dim3(16, 8), NTHR, SMEM_BYTES>>>(W_hh);
    gather_kernel<<<BB * NT * 64 / 1024, 256>>>((float4*)d_out);
}